// round 15
// baseline (speedup 1.0000x reference)
#include <cuda_runtime.h>
#include <cstdint>

#define NB 128
#define TILE 64
#define US 68
#define N_ATOMS_MAX 50000

typedef unsigned long long ull;

// Scratch (device globals: allocation-free per harness rules)
__device__ float g_h[N_ATOMS_MAX * NB];
__device__ float g_agg[N_ATOMS_MAX * NB];
__device__ float g_t[N_ATOMS_MAX * NB];

// ---------------- helpers ----------------

__device__ __forceinline__ float sspf(float x) {
    float e = __expf(-fabsf(x));
    return fmaxf(x, 0.0f) + __logf(1.0f + e) - 0.69314718055994531f;
}
__device__ __forceinline__ ull pack2(float x, float y) {
    ull r; asm("mov.b64 %0, {%1, %2};" : "=l"(r) : "f"(x), "f"(y)); return r;
}
__device__ __forceinline__ ull dupf(float w) {
    ull r; asm("mov.b64 %0, {%1, %1};" : "=l"(r) : "f"(w)); return r;
}
__device__ __forceinline__ void unpack2(ull v, float& x, float& y) {
    asm("mov.b64 {%0, %1}, %2;" : "=f"(x), "=f"(y) : "l"(v));
}
__device__ __forceinline__ void fma2(ull& d, ull a, ull b) {
    asm("fma.rn.f32x2 %0, %1, %2, %3;" : "=l"(d) : "l"(a), "l"(b), "l"(d));
}
__device__ __forceinline__ void red4(float* p, float a, float b, float c, float d) {
    asm volatile("red.global.add.v4.f32 [%0], {%1,%2,%3,%4};"
                 :: "l"(p), "f"(a), "f"(b), "f"(c), "f"(d) : "memory");
}

// ---------------- zero / dummy ----------------
__global__ void zero_kernel(float4* __restrict__ p, int n4) {
    int i = blockIdx.x * blockDim.x + threadIdx.x;
    if (i < n4) p[i] = make_float4(0.f, 0.f, 0.f, 0.f);
}
__global__ void dummy_kernel() {}

// ---------------- row GEMM: Y = [ssp](X @ W + b), K=N=128, 4 rows/iter ----
template <bool DOSSP>
__global__ __launch_bounds__(128, 2) void rowmm_kernel(
    const float* __restrict__ X, const float* __restrict__ W,
    const float* __restrict__ b, float* __restrict__ Y, int nrows) {
    const int j = threadIdx.x;
    float wr[NB];
#pragma unroll
    for (int k = 0; k < NB; k++) wr[k] = W[k * NB + j];
    const float bj = b[j];
    __shared__ __align__(16) float xsh[NB * 4];
    const int ngroups = (nrows + 3) / 4;
    for (int g = blockIdx.x; g < ngroups; g += gridDim.x) {
        const int row0 = g * 4;
        __syncthreads();
#pragma unroll
        for (int r = 0; r < 4; r++) {
            int row = row0 + r;
            xsh[j * 4 + r] = (row < nrows) ? X[row * NB + j] : 0.0f;
        }
        __syncthreads();
        ull a01 = pack2(bj, bj), a23 = a01;
        const ulonglong2* xs2 = (const ulonglong2*)xsh;
#pragma unroll
        for (int k = 0; k < NB; k++) {
            ulonglong2 uv = xs2[k];
            ull wd = dupf(wr[k]);
            fma2(a01, uv.x, wd);
            fma2(a23, uv.y, wd);
        }
        float y0, y1, y2, y3;
        unpack2(a01, y0, y1); unpack2(a23, y2, y3);
        if (DOSSP) { y0 = sspf(y0); y1 = sspf(y1); y2 = sspf(y2); y3 = sspf(y3); }
        float yv[4] = {y0, y1, y2, y3};
#pragma unroll
        for (int r = 0; r < 4; r++) {
            int row = row0 + r;
            if (row < nrows) Y[row * NB + j] = yv[r];
        }
    }
}

// ---------------- pair kernel: 512 threads, 4p x 4c tile, W2 via L1 ----------------
// smem float offsets
#define SM_F    0                     // 20*US  = 1360
#define SM_W1   1360                  // 20*128 = 2560
#define SM_U    3920                  // 128*US = 8704
#define SM_II   12624
#define SM_IJ   12688
#define SM_RC   12752
#define SM_FLOATS 12816
#define SM_BYTES (SM_FLOATS * 4)

__global__ __launch_bounds__(512, 2) void pair_kernel(
    const float* __restrict__ f_ij, const float* __restrict__ rcut,
    const float* __restrict__ Wf1, const float* __restrict__ bf1,
    const float* __restrict__ Wf2, const float* __restrict__ bf2,
    const int* __restrict__ idx_i, const int* __restrict__ idx_j,
    const float* __restrict__ h, float* __restrict__ agg, int npairs) {
    extern __shared__ __align__(16) float sm[];
    float* fs  = sm + SM_F;
    float* w1s = sm + SM_W1;
    float* us  = sm + SM_U;
    int*   iis = (int*)(sm + SM_II);
    int*   ijs = (int*)(sm + SM_IJ);
    float* rcs = sm + SM_RC;

    const int tid  = threadIdx.x;
    const int wid  = tid >> 5;
    const int lane = tid & 31;

    // persistent: Wf1 -> smem
    for (int i = tid; i < 20 * NB; i += 512) w1s[i] = Wf1[i];

    // stage-1 ownership: column j1, pair quarter qh (16 pairs)
    const int j1 = tid & 127;
    const int qh = tid >> 7;          // 0..3
    const float b1 = bf1[j1];

    // stage-2 thread tile: 4 pairs x 4 cols
    const int pairg = ((wid & 1) << 3) | (lane >> 2);   // 0..15
    const int pr0   = pairg << 2;
    const int colg  = ((wid >> 1) << 2) | (lane & 3);   // 0..31
    const int c0    = colg << 2;
    const float4 b2v = *(const float4*)(bf2 + c0);

    const int ntiles = (npairs + TILE - 1) / TILE;
    for (int t = blockIdx.x; t < ntiles; t += gridDim.x) {
        const int base = t * TILE;
        __syncthreads();  // prev tile's u reads + epilogue done

        // --- f tile load + transpose to fs[k][p] ---
        if (base + TILE <= npairs) {
            for (int vi = tid; vi < TILE * 5; vi += 512) {
                float4 v = ((const float4*)f_ij)[base * 5 + vi];
                int g = vi * 4;
                int p = g / 20, k = g - p * 20;   // k in {0,4,8,12,16}
                fs[(k + 0) * US + p] = v.x;
                fs[(k + 1) * US + p] = v.y;
                fs[(k + 2) * US + p] = v.z;
                fs[(k + 3) * US + p] = v.w;
            }
        } else {
            for (int vi = tid; vi < TILE * 20; vi += 512) {
                int p = vi / 20, k = vi - p * 20;
                int e = base + p;
                fs[k * US + p] = (e < npairs) ? f_ij[e * 20 + k] : 0.0f;
            }
        }
        if (tid < TILE) {
            int e = base + tid;
            bool v = (e < npairs);
            iis[tid] = v ? idx_i[e] : 0;
            ijs[tid] = v ? idx_j[e] : 0;
            rcs[tid] = v ? rcut[e] : 0.0f;
        }
        __syncthreads();

        // --- stage 1: u[j1][qh*16..+16] = ssp(f @ Wf1[:,j1] + b1) ---
        {
            ull a[8];
            ull bi = pack2(b1, b1);
#pragma unroll
            for (int i = 0; i < 8; i++) a[i] = bi;
#pragma unroll
            for (int k = 0; k < 20; k++) {
                const ulonglong2* fp = (const ulonglong2*)(fs + k * US + (qh << 4));
                ull wd = dupf(w1s[k * NB + j1]);
#pragma unroll
                for (int q = 0; q < 4; q++) {
                    ulonglong2 fv = fp[q];
                    fma2(a[2 * q], fv.x, wd);
                    fma2(a[2 * q + 1], fv.y, wd);
                }
            }
            float v[16];
#pragma unroll
            for (int i = 0; i < 8; i++) unpack2(a[i], v[2 * i], v[2 * i + 1]);
#pragma unroll
            for (int i = 0; i < 16; i++) v[i] = sspf(v[i]);
#pragma unroll
            for (int q = 0; q < 4; q++)
                *(float4*)(us + j1 * US + (qh << 4) + q * 4) =
                    make_float4(v[4 * q], v[4 * q + 1], v[4 * q + 2], v[4 * q + 3]);
        }
        __syncthreads();

        // --- stage 2: acc[4 cols][2 pair-pairs] over k = 0..127 ---
        // acc[c*2+pp] = packed (pair pr0+2pp, pr0+2pp+1) for col c0+c
        ull acc[8];
        acc[0] = pack2(b2v.x, b2v.x); acc[1] = acc[0];
        acc[2] = pack2(b2v.y, b2v.y); acc[3] = acc[2];
        acc[4] = pack2(b2v.z, b2v.z); acc[5] = acc[4];
        acc[6] = pack2(b2v.w, b2v.w); acc[7] = acc[6];
        {
            const float* upb = us + pr0;
            const float* wpb = Wf2 + c0;
#pragma unroll 8
            for (int k = 0; k < NB; k++) {
                ulonglong2 ua = *(const ulonglong2*)(upb + k * US);   // 4 pairs, LDS broadcast
                float4 wv = __ldg((const float4*)(wpb + (k << 7)));   // 4 cols, L1-resident
                ull w0 = dupf(wv.x), w1 = dupf(wv.y), w2 = dupf(wv.z), w3 = dupf(wv.w);
                fma2(acc[0], ua.x, w0); fma2(acc[1], ua.y, w0);
                fma2(acc[2], ua.x, w1); fma2(acc[3], ua.y, w1);
                fma2(acc[4], ua.x, w2); fma2(acc[5], ua.y, w2);
                fma2(acc[6], ua.x, w3); fma2(acc[7], ua.y, w3);
            }
        }

        // --- epilogue: direct register scatter (cols c0..c0+3 contiguous) ---
#pragma unroll
        for (int pp = 0; pp < 2; pp++) {
            int p_lo = pr0 + 2 * pp, p_hi = p_lo + 1;
            float rl = rcs[p_lo], rh = rcs[p_hi];
            int il = iis[p_lo], ih = iis[p_hi];
            int jl = ijs[p_lo], jh = ijs[p_hi];
            float4 hl = *(const float4*)(h + (size_t)jl * NB + c0);
            float4 hh = *(const float4*)(h + (size_t)jh * NB + c0);
            float lo[4], hi[4];
#pragma unroll
            for (int q = 0; q < 4; q++) unpack2(acc[q * 2 + pp], lo[q], hi[q]);
            red4(agg + (size_t)il * NB + c0,
                 lo[0] * rl * hl.x, lo[1] * rl * hl.y,
                 lo[2] * rl * hl.z, lo[3] * rl * hl.w);
            red4(agg + (size_t)ih * NB + c0,
                 hi[0] * rh * hh.x, hi[1] * rh * hh.y,
                 hi[2] * rh * hh.z, hi[3] * rh * hh.w);
        }
    }
}

// ---------------- launch ----------------
extern "C" void kernel_launch(void* const* d_in, const int* in_sizes, int n_in,
                              void* d_out, int out_size) {
    const float* x    = (const float*)d_in[0];
    const float* f_ij = (const float*)d_in[1];
    const float* rcut = (const float*)d_in[2];
    const float* W_in = (const float*)d_in[3];
    const float* b_in = (const float*)d_in[4];
    const float* Wf1  = (const float*)d_in[5];
    const float* bf1  = (const float*)d_in[6];
    const float* Wf2  = (const float*)d_in[7];
    const float* bf2  = (const float*)d_in[8];
    const float* Wo1  = (const float*)d_in[9];
    const float* bo1  = (const float*)d_in[10];
    const float* Wo2  = (const float*)d_in[11];
    const float* bo2  = (const float*)d_in[12];
    const int* idx_i  = (const int*)d_in[13];
    const int* idx_j  = (const int*)d_in[14];

    const int natoms = in_sizes[0] / NB;
    const int npairs = in_sizes[2];
    float* out = (float*)d_out;

    float *hp, *aggp, *tp;
    cudaGetSymbolAddress((void**)&hp, g_h);
    cudaGetSymbolAddress((void**)&aggp, g_agg);
    cudaGetSymbolAddress((void**)&tp, g_t);

    static const bool once = []() {
        cudaFuncSetAttribute(pair_kernel,
                             cudaFuncAttributeMaxDynamicSharedMemorySize, SM_BYTES);
        return true;
    }();
    (void)once;

    const int grid = 148 * 8;
    const int n4 = natoms * NB / 4;
    zero_kernel<<<(n4 + 255) / 256, 256>>>((float4*)aggp, n4);
    rowmm_kernel<false><<<grid, 128>>>(x, W_in, b_in, hp, natoms);
    dummy_kernel<<<1, 32>>>();
    pair_kernel<<<148 * 2, 512, SM_BYTES>>>(f_ij, rcut, Wf1, bf1, Wf2, bf2,
                                            idx_i, idx_j, hp, aggp, npairs);
    rowmm_kernel<true><<<grid, 128>>>(aggp, Wo1, bo1, tp, natoms);
    rowmm_kernel<false><<<grid, 128>>>(tp, Wo2, bo2, out, natoms);
}